// round 6
// baseline (speedup 1.0000x reference)
#include <cuda_runtime.h>
#include <cuda_bf16.h>
#include <cstdint>
#include <math.h>

// ============================================================================
// AutoEncoder via mma.sync (HMMA), bf16 hi/lo split (3 products).
// R5: 128x256 tile / 512 threads / 3-stage ring; prep batched to 4 launches
//     so ncu (-s 5 -c 1) captures the L2 GEMM.
// ============================================================================

#define BATCH 8192

__device__ __forceinline__ uint32_t smem_u32(const void* p) {
    uint32_t a;
    asm("{ .reg .u64 t; cvta.to.shared.u64 t, %1; cvt.u32.u64 %0, t; }"
        : "=r"(a) : "l"(p));
    return a;
}
__device__ __forceinline__ void cp_async16(uint32_t dst, const void* src) {
    asm volatile("cp.async.cg.shared.global [%0], [%1], 16;" :: "r"(dst), "l"(src));
}
__device__ __forceinline__ void cp_commit() {
    asm volatile("cp.async.commit_group;" ::: "memory");
}
template <int N> __device__ __forceinline__ void cp_wait() {
    asm volatile("cp.async.wait_group %0;" :: "n"(N) : "memory");
}
__device__ __forceinline__ void ldsm4(uint32_t* r, uint32_t a) {
    asm volatile("ldmatrix.sync.aligned.m8n8.x4.shared.b16 {%0,%1,%2,%3}, [%4];"
                 : "=r"(r[0]), "=r"(r[1]), "=r"(r[2]), "=r"(r[3]) : "r"(a));
}
__device__ __forceinline__ void mma16816(float* d, const uint32_t* a, const uint32_t* b) {
    asm volatile("mma.sync.aligned.m16n8k16.row.col.f32.bf16.bf16.f32 "
                 "{%0,%1,%2,%3}, {%4,%5,%6,%7}, {%8,%9}, {%0,%1,%2,%3};"
                 : "+f"(d[0]), "+f"(d[1]), "+f"(d[2]), "+f"(d[3])
                 : "r"(a[0]), "r"(a[1]), "r"(a[2]), "r"(a[3]),
                   "r"(b[0]), "r"(b[1]));
}
// 64B logical rows packed pairwise into 128B atoms + SW128 XOR swizzle.
__device__ __forceinline__ uint32_t tile_off(int r, int c) {
    uint32_t o = ((uint32_t)(r >> 1) << 7) + ((uint32_t)(r & 1) << 6) +
                 ((uint32_t)c << 4);
    return o ^ ((o >> 3) & 0x70);
}

// ---------------------------------------------------------------------------
// Device global scratch
// ---------------------------------------------------------------------------
__device__ __align__(16) __nv_bfloat16 g_bufA_h[(size_t)BATCH * 2048];
__device__ __align__(16) __nv_bfloat16 g_bufA_l[(size_t)BATCH * 2048];
__device__ __align__(16) __nv_bfloat16 g_bufB_h[(size_t)BATCH * 2048];
__device__ __align__(16) __nv_bfloat16 g_bufB_l[(size_t)BATCH * 2048];
__device__ __align__(16) __nv_bfloat16 g_ctrl_h[(size_t)BATCH * 64];
__device__ __align__(16) __nv_bfloat16 g_ctrl_l[(size_t)BATCH * 64];

#define OFF_We1 0u
#define OFF_We2 (OFF_We1 + 2048u*1024u)
#define OFF_We3 (OFF_We2 + 2048u*2048u)
#define OFF_Wd1 (OFF_We3 + 64u*2048u)
#define OFF_Wd2 (OFF_Wd1 + 2048u*64u)
#define OFF_Wd3 (OFF_Wd2 + 2048u*2048u)
#define W_TOTAL (OFF_Wd3 + 1024u*2048u)
__device__ __align__(16) __nv_bfloat16 g_Wh[W_TOTAL];
__device__ __align__(16) __nv_bfloat16 g_Wl[W_TOTAL];

// ---------------------------------------------------------------------------
// Prep kernels (batched: 4 launches total before the GEMM chain)
// ---------------------------------------------------------------------------
__global__ void split_convert(const float* __restrict__ X,
                              __nv_bfloat16* __restrict__ H,
                              __nv_bfloat16* __restrict__ L, int n4) {
    int i = blockIdx.x * blockDim.x + threadIdx.x;
    if (i >= n4) return;
    float4 x = reinterpret_cast<const float4*>(X)[i];
    __nv_bfloat16 h0 = __float2bfloat16(x.x), h1 = __float2bfloat16(x.y);
    __nv_bfloat16 h2 = __float2bfloat16(x.z), h3 = __float2bfloat16(x.w);
    __nv_bfloat16 l0 = __float2bfloat16(x.x - __bfloat162float(h0));
    __nv_bfloat16 l1 = __float2bfloat16(x.y - __bfloat162float(h1));
    __nv_bfloat16 l2 = __float2bfloat16(x.z - __bfloat162float(h2));
    __nv_bfloat16 l3 = __float2bfloat16(x.w - __bfloat162float(h3));
    reinterpret_cast<__nv_bfloat162*>(H)[i * 2 + 0] = __halves2bfloat162(h0, h1);
    reinterpret_cast<__nv_bfloat162*>(H)[i * 2 + 1] = __halves2bfloat162(h2, h3);
    reinterpret_cast<__nv_bfloat162*>(L)[i * 2 + 0] = __halves2bfloat162(l0, l1);
    reinterpret_cast<__nv_bfloat162*>(L)[i * 2 + 1] = __halves2bfloat162(l2, l3);
}

// two transposes per launch, selected by blockIdx.z; out-of-range tiles exit
__global__ void transpose_split2(const float* __restrict__ W0, __nv_bfloat16* Th0,
                                 __nv_bfloat16* Tl0, int K0, int N0,
                                 const float* __restrict__ W1, __nv_bfloat16* Th1,
                                 __nv_bfloat16* Tl1, int K1, int N1) {
    const float* W;  __nv_bfloat16 *Th, *Tl;  int K, N;
    if (blockIdx.z == 0) { W = W0; Th = Th0; Tl = Tl0; K = K0; N = N0; }
    else                 { W = W1; Th = Th1; Tl = Tl1; K = K1; N = N1; }
    int k0 = blockIdx.x * 32, n0 = blockIdx.y * 32;
    if (k0 >= K || n0 >= N) return;
    __shared__ float t[32][33];
    int tx = threadIdx.x, ty = threadIdx.y;
    for (int r = ty; r < 32; r += 8)
        t[r][tx] = W[(size_t)(k0 + r) * N + n0 + tx];
    __syncthreads();
    for (int r = ty; r < 32; r += 8) {
        float v = t[tx][r];
        size_t o = (size_t)(n0 + r) * K + k0 + tx;
        __nv_bfloat16 h = __float2bfloat16(v);
        Th[o] = h;
        Tl[o] = __float2bfloat16(v - __bfloat162float(h));
    }
}

// ---------------------------------------------------------------------------
// mma.sync GEMM, STAGES-stage pipeline, 1 sync/iter.
// OUTMODE: 0 = f32 only, 1 = bf16 hi/lo pair only, 2 = both
// ---------------------------------------------------------------------------
template <int BM, int BN, int WARPS_M, int WARPS_N, int STAGES, int OUTMODE>
__global__ __launch_bounds__(WARPS_M * WARPS_N * 32, 1)
void gemm_mma(const __nv_bfloat16* __restrict__ Ah, const __nv_bfloat16* __restrict__ Al,
              const __nv_bfloat16* __restrict__ Bh, const __nv_bfloat16* __restrict__ Bl,
              const float* __restrict__ bias,
              float* __restrict__ Cf,
              __nv_bfloat16* __restrict__ Ch, __nv_bfloat16* __restrict__ Cl,
              int N, int K, int act)
{
    constexpr int THREADS = WARPS_M * WARPS_N * 32;
    constexpr int BK = 32;
    constexpr int WM = BM / WARPS_M, WN = BN / WARPS_N;
    constexpr int MW = WM / 16, NW = WN / 8;
    constexpr int NW2 = (NW > 4) ? 4 : NW;       // B-fragment chunk size
    constexpr int ASZ = BM * 64;                 // bytes/operand/stage
    constexpr int BSZ = BN * 64;
    constexpr int SSZ = 2 * ASZ + 2 * BSZ;

    extern __shared__ __align__(128) char sm[];
    const uint32_t sb = smem_u32(sm);
    const int tid = threadIdx.x, wid = tid >> 5, lid = tid & 31;
    const int row0 = blockIdx.y * BM, col0 = blockIdx.x * BN;
    const int KT = K / BK;

    const int wm0 = (wid % WARPS_M) * WM;
    const int wn0 = (wid / WARPS_M) * WN;
    const int mat = lid >> 3, mr = lid & 7;

    float acc[MW][NW][4];
#pragma unroll
    for (int i = 0; i < MW; i++)
#pragma unroll
        for (int j = 0; j < NW; j++)
#pragma unroll
            for (int q = 0; q < 4; q++) acc[i][j][q] = 0.0f;

    auto load_stage = [&](int kt, int s) {
        const uint32_t st = sb + s * SSZ;
        const int k0 = kt * BK;
#pragma unroll
        for (int ch = tid; ch < BM * 4; ch += THREADS) {
            int r = ch >> 2, c = ch & 3;
            size_t g = (size_t)(row0 + r) * K + k0 + c * 8;
            uint32_t so = st + tile_off(r, c);
            cp_async16(so, Ah + g);
            cp_async16(so + ASZ, Al + g);
        }
#pragma unroll
        for (int ch = tid; ch < BN * 4; ch += THREADS) {
            int r = ch >> 2, c = ch & 3;
            size_t g = (size_t)(col0 + r) * K + k0 + c * 8;
            uint32_t so = st + 2 * ASZ + tile_off(r, c);
            cp_async16(so, Bh + g);
            cp_async16(so + BSZ, Bl + g);
        }
    };

    int arow[MW], brow[NW / 2];
#pragma unroll
    for (int i = 0; i < MW; i++) arow[i] = wm0 + i * 16 + (mat & 1) * 8 + mr;
#pragma unroll
    for (int j = 0; j < NW / 2; j++) brow[j] = wn0 + j * 16 + (mat >> 1) * 8 + mr;

#pragma unroll
    for (int p = 0; p < STAGES - 1; p++) {
        if (p < KT) load_stage(p, p);
        cp_commit();
    }

    for (int kt = 0; kt < KT; kt++) {
        cp_wait<STAGES - 2>();
        __syncthreads();

        if (kt + STAGES - 1 < KT) load_stage(kt + STAGES - 1, (kt + STAGES - 1) % STAGES);
        cp_commit();

        const int s = kt % STAGES;
        const uint32_t stA  = sb + s * SSZ;
        const uint32_t stAl = stA + ASZ;
        const uint32_t stB  = stA + 2 * ASZ;
        const uint32_t stBl = stB + BSZ;

#pragma unroll
        for (int ks = 0; ks < 2; ks++) {
            uint32_t ah[MW][4], al[MW][4];
#pragma unroll
            for (int i = 0; i < MW; i++) {
                uint32_t off = tile_off(arow[i], 2 * ks + (mat >> 1));
                ldsm4(ah[i], stA + off);
                ldsm4(al[i], stAl + off);
            }
#pragma unroll
            for (int nh = 0; nh < NW / NW2; nh++) {
                uint32_t bh[NW2][2], bl[NW2][2];
#pragma unroll
                for (int j = 0; j < NW2 / 2; j++) {
                    uint32_t off = tile_off(brow[nh * (NW2 / 2) + j], 2 * ks + (mat & 1));
                    uint32_t t[4];
                    ldsm4(t, stB + off);
                    bh[2 * j][0] = t[0]; bh[2 * j][1] = t[1];
                    bh[2 * j + 1][0] = t[2]; bh[2 * j + 1][1] = t[3];
                    ldsm4(t, stBl + off);
                    bl[2 * j][0] = t[0]; bl[2 * j][1] = t[1];
                    bl[2 * j + 1][0] = t[2]; bl[2 * j + 1][1] = t[3];
                }
#pragma unroll
                for (int i = 0; i < MW; i++)
#pragma unroll
                    for (int j = 0; j < NW2; j++) {
                        float* a = acc[i][nh * NW2 + j];
                        mma16816(a, ah[i], bh[j]);  // hh
                        mma16816(a, ah[i], bl[j]);  // hl
                        mma16816(a, al[i], bh[j]);  // lh
                    }
            }
        }
    }

    // ---- epilogue ----
    const int lm = lid >> 2, ln2 = (lid & 3) * 2;
#pragma unroll
    for (int i = 0; i < MW; i++)
#pragma unroll
        for (int j = 0; j < NW; j++)
#pragma unroll
            for (int h = 0; h < 2; h++) {
                int gm = row0 + wm0 + i * 16 + h * 8 + lm;
                int gn = col0 + wn0 + j * 8 + ln2;
                float v0 = acc[i][j][2 * h + 0] + __ldg(bias + gn);
                float v1 = acc[i][j][2 * h + 1] + __ldg(bias + gn + 1);
                if (act == 1) { v0 = fmaxf(v0, 0.f); v1 = fmaxf(v1, 0.f); }
                else if (act == 2) {
                    v0 = 1.0f / (1.0f + expf(-v0));
                    v1 = 1.0f / (1.0f + expf(-v1));
                }
                size_t o = (size_t)gm * N + gn;
                if (OUTMODE == 0 || OUTMODE == 2)
                    *reinterpret_cast<float2*>(Cf + o) = make_float2(v0, v1);
                if (OUTMODE == 1 || OUTMODE == 2) {
                    __nv_bfloat16 h0 = __float2bfloat16(v0);
                    __nv_bfloat16 h1 = __float2bfloat16(v1);
                    __nv_bfloat16 l0 = __float2bfloat16(v0 - __bfloat162float(h0));
                    __nv_bfloat16 l1 = __float2bfloat16(v1 - __bfloat162float(h1));
                    *reinterpret_cast<__nv_bfloat162*>(Ch + o) = __halves2bfloat162(h0, h1);
                    *reinterpret_cast<__nv_bfloat162*>(Cl + o) = __halves2bfloat162(l0, l1);
                }
            }
}

// ---------------------------------------------------------------------------
// Host launch
// ---------------------------------------------------------------------------
extern "C" void kernel_launch(void* const* d_in, const int* in_sizes, int n_in,
                              void* d_out, int out_size) {
    const float* x   = (const float*)d_in[0];
    const float* We1 = (const float*)d_in[1];
    const float* be1 = (const float*)d_in[2];
    const float* We2 = (const float*)d_in[3];
    const float* be2 = (const float*)d_in[4];
    const float* We3 = (const float*)d_in[5];
    const float* be3 = (const float*)d_in[6];
    const float* Wd1 = (const float*)d_in[7];
    const float* bd1 = (const float*)d_in[8];
    const float* Wd2 = (const float*)d_in[9];
    const float* bd2 = (const float*)d_in[10];
    const float* Wd3 = (const float*)d_in[11];
    const float* bd3 = (const float*)d_in[12];

    float* out = (float*)d_out;
    float* control = out;
    float* state   = out + (size_t)BATCH * 64;

    __nv_bfloat16 *bufAh, *bufAl, *bufBh, *bufBl, *ctrlh, *ctrll, *Wh, *Wl;
    cudaGetSymbolAddress((void**)&bufAh, g_bufA_h);
    cudaGetSymbolAddress((void**)&bufAl, g_bufA_l);
    cudaGetSymbolAddress((void**)&bufBh, g_bufB_h);
    cudaGetSymbolAddress((void**)&bufBl, g_bufB_l);
    cudaGetSymbolAddress((void**)&ctrlh, g_ctrl_h);
    cudaGetSymbolAddress((void**)&ctrll, g_ctrl_l);
    cudaGetSymbolAddress((void**)&Wh, g_Wh);
    cudaGetSymbolAddress((void**)&Wl, g_Wl);

    // big kernel: 128x256 tile, 512 threads, 3 stages
    constexpr int SMEM_BIG   = 3 * (2 * 128 * 64 + 2 * 256 * 64);  // 147456
    constexpr int SMEM_SMALL = 4 * (2 * 64 * 64 + 2 * 64 * 64);    // 65536
    cudaFuncSetAttribute((const void*)gemm_mma<128,256,4,4,3,0>,
                         cudaFuncAttributeMaxDynamicSharedMemorySize, SMEM_BIG);
    cudaFuncSetAttribute((const void*)gemm_mma<128,256,4,4,3,1>,
                         cudaFuncAttributeMaxDynamicSharedMemorySize, SMEM_BIG);
    cudaFuncSetAttribute((const void*)gemm_mma<64,64,4,2,4,2>,
                         cudaFuncAttributeMaxDynamicSharedMemorySize, SMEM_SMALL);

    // ---- prep: exactly 4 launches (ncu -s 5 then lands on GEMM L2) ----
    {
        int n4 = BATCH * 1024 / 4;
        split_convert<<<(n4 + 255) / 256, 256>>>(x, bufBh, bufBl, n4);
    }
    dim3 tb(32, 8);
    transpose_split2<<<dim3(64, 64, 2), tb>>>(
        We1, Wh + OFF_We1, Wl + OFF_We1, 1024, 2048,
        Wd3, Wh + OFF_Wd3, Wl + OFF_Wd3, 2048, 1024);
    transpose_split2<<<dim3(64, 64, 2), tb>>>(
        We2, Wh + OFF_We2, Wl + OFF_We2, 2048, 2048,
        Wd2, Wh + OFF_Wd2, Wl + OFF_Wd2, 2048, 2048);
    transpose_split2<<<dim3(64, 64, 2), tb>>>(
        We3, Wh + OFF_We3, Wl + OFF_We3, 2048, 64,
        Wd1, Wh + OFF_Wd1, Wl + OFF_Wd1, 64, 2048);

    // L1: x @ We1 -> relu (N=2048, K=1024)
    gemm_mma<128,256,4,4,3,1><<<dim3(8, 64), 512, SMEM_BIG>>>(
        bufBh, bufBl, Wh + OFF_We1, Wl + OFF_We1, be1,
        nullptr, bufAh, bufAl, 2048, 1024, 1);
    // L2: @ We2 -> relu (N=2048, K=2048)   <-- profiled launch
    gemm_mma<128,256,4,4,3,1><<<dim3(8, 64), 512, SMEM_BIG>>>(
        bufAh, bufAl, Wh + OFF_We2, Wl + OFF_We2, be2,
        nullptr, bufBh, bufBl, 2048, 2048, 1);
    // L3: @ We3 -> sigmoid (N=64, K=2048)
    gemm_mma<64,64,4,2,4,2><<<dim3(1, 128), 256, SMEM_SMALL>>>(
        bufBh, bufBl, Wh + OFF_We3, Wl + OFF_We3, be3,
        control, ctrlh, ctrll, 64, 2048, 2);
    // L4: @ Wd1 -> relu (N=2048, K=64)
    gemm_mma<128,256,4,4,3,1><<<dim3(8, 64), 512, SMEM_BIG>>>(
        ctrlh, ctrll, Wh + OFF_Wd1, Wl + OFF_Wd1, bd1,
        nullptr, bufAh, bufAl, 2048, 64, 1);
    // L5: @ Wd2 -> relu (N=2048, K=2048)
    gemm_mma<128,256,4,4,3,1><<<dim3(8, 64), 512, SMEM_BIG>>>(
        bufAh, bufAl, Wh + OFF_Wd2, Wl + OFF_Wd2, bd2,
        nullptr, bufBh, bufBl, 2048, 2048, 1);
    // L6: @ Wd3 -> linear f32 (N=1024, K=2048)
    gemm_mma<128,256,4,4,3,0><<<dim3(4, 64), 512, SMEM_BIG>>>(
        bufBh, bufBl, Wh + OFF_Wd3, Wl + OFF_Wd3, bd3,
        state, nullptr, nullptr, 1024, 2048, 0);

    (void)in_sizes; (void)n_in; (void)out_size;
}

// round 7
// speedup vs baseline: 1.0849x; 1.0849x over previous
#include <cuda_runtime.h>
#include <cuda_bf16.h>
#include <cstdint>
#include <math.h>

// ============================================================================
// AutoEncoder via mma.sync (HMMA), bf16 hi/lo split (3 products).
// R6: R4 config (128x128, 8 warps, 4-stage ring) + 3-pass mma reorder to
//     break accumulator RAW chains + single fused prep launch.
// ============================================================================

#define BATCH 8192

__device__ __forceinline__ uint32_t smem_u32(const void* p) {
    uint32_t a;
    asm("{ .reg .u64 t; cvta.to.shared.u64 t, %1; cvt.u32.u64 %0, t; }"
        : "=r"(a) : "l"(p));
    return a;
}
__device__ __forceinline__ void cp_async16(uint32_t dst, const void* src) {
    asm volatile("cp.async.cg.shared.global [%0], [%1], 16;" :: "r"(dst), "l"(src));
}
__device__ __forceinline__ void cp_commit() {
    asm volatile("cp.async.commit_group;" ::: "memory");
}
template <int N> __device__ __forceinline__ void cp_wait() {
    asm volatile("cp.async.wait_group %0;" :: "n"(N) : "memory");
}
__device__ __forceinline__ void ldsm4(uint32_t* r, uint32_t a) {
    asm volatile("ldmatrix.sync.aligned.m8n8.x4.shared.b16 {%0,%1,%2,%3}, [%4];"
                 : "=r"(r[0]), "=r"(r[1]), "=r"(r[2]), "=r"(r[3]) : "r"(a));
}
__device__ __forceinline__ void mma16816(float* d, const uint32_t* a, const uint32_t* b) {
    asm volatile("mma.sync.aligned.m16n8k16.row.col.f32.bf16.bf16.f32 "
                 "{%0,%1,%2,%3}, {%4,%5,%6,%7}, {%8,%9}, {%0,%1,%2,%3};"
                 : "+f"(d[0]), "+f"(d[1]), "+f"(d[2]), "+f"(d[3])
                 : "r"(a[0]), "r"(a[1]), "r"(a[2]), "r"(a[3]),
                   "r"(b[0]), "r"(b[1]));
}
// 64B logical rows packed pairwise into 128B atoms + SW128 XOR swizzle.
__device__ __forceinline__ uint32_t tile_off(int r, int c) {
    uint32_t o = ((uint32_t)(r >> 1) << 7) + ((uint32_t)(r & 1) << 6) +
                 ((uint32_t)c << 4);
    return o ^ ((o >> 3) & 0x70);
}

// ---------------------------------------------------------------------------
// Device global scratch
// ---------------------------------------------------------------------------
__device__ __align__(16) __nv_bfloat16 g_bufA_h[(size_t)BATCH * 2048];
__device__ __align__(16) __nv_bfloat16 g_bufA_l[(size_t)BATCH * 2048];
__device__ __align__(16) __nv_bfloat16 g_bufB_h[(size_t)BATCH * 2048];
__device__ __align__(16) __nv_bfloat16 g_bufB_l[(size_t)BATCH * 2048];
__device__ __align__(16) __nv_bfloat16 g_ctrl_h[(size_t)BATCH * 64];
__device__ __align__(16) __nv_bfloat16 g_ctrl_l[(size_t)BATCH * 64];

#define OFF_We1 0u
#define OFF_We2 (OFF_We1 + 2048u*1024u)
#define OFF_We3 (OFF_We2 + 2048u*2048u)
#define OFF_Wd1 (OFF_We3 + 64u*2048u)
#define OFF_Wd2 (OFF_Wd1 + 2048u*64u)
#define OFF_Wd3 (OFF_Wd2 + 2048u*2048u)
#define W_TOTAL (OFF_Wd3 + 1024u*2048u)
__device__ __align__(16) __nv_bfloat16 g_Wh[W_TOTAL];
__device__ __align__(16) __nv_bfloat16 g_Wl[W_TOTAL];

// ---------------------------------------------------------------------------
// Fused prep: ONE launch. z=0: split x; z=1..6: transpose+split weights.
// ---------------------------------------------------------------------------
__global__ void prep_all(const float* __restrict__ x,
                         __nv_bfloat16* __restrict__ xh, __nv_bfloat16* __restrict__ xl,
                         const float* We1, const float* We2, const float* We3,
                         const float* Wd1, const float* Wd2, const float* Wd3,
                         __nv_bfloat16* __restrict__ Wh, __nv_bfloat16* __restrict__ Wl)
{
    const int z = blockIdx.z;
    if (z == 0) {
        // split x: 8192*1024 floats = 2,097,152 float4; 4096 blocks*256thr*2
        int tid = threadIdx.y * 32 + threadIdx.x;
        int bid = blockIdx.y * 64 + blockIdx.x;
        int base = (bid * 256 + tid) * 2;
#pragma unroll
        for (int u = 0; u < 2; u++) {
            int i = base + u;
            float4 v = reinterpret_cast<const float4*>(x)[i];
            __nv_bfloat16 h0 = __float2bfloat16(v.x), h1 = __float2bfloat16(v.y);
            __nv_bfloat16 h2 = __float2bfloat16(v.z), h3 = __float2bfloat16(v.w);
            __nv_bfloat16 l0 = __float2bfloat16(v.x - __bfloat162float(h0));
            __nv_bfloat16 l1 = __float2bfloat16(v.y - __bfloat162float(h1));
            __nv_bfloat16 l2 = __float2bfloat16(v.z - __bfloat162float(h2));
            __nv_bfloat16 l3 = __float2bfloat16(v.w - __bfloat162float(h3));
            reinterpret_cast<__nv_bfloat162*>(xh)[i * 2 + 0] = __halves2bfloat162(h0, h1);
            reinterpret_cast<__nv_bfloat162*>(xh)[i * 2 + 1] = __halves2bfloat162(h2, h3);
            reinterpret_cast<__nv_bfloat162*>(xl)[i * 2 + 0] = __halves2bfloat162(l0, l1);
            reinterpret_cast<__nv_bfloat162*>(xl)[i * 2 + 1] = __halves2bfloat162(l2, l3);
        }
        return;
    }
    const float* W; uint32_t off; int K, N;
    switch (z) {
        case 1: W = We1; off = OFF_We1; K = 1024; N = 2048; break;
        case 2: W = We2; off = OFF_We2; K = 2048; N = 2048; break;
        case 3: W = We3; off = OFF_We3; K = 2048; N = 64;   break;
        case 4: W = Wd1; off = OFF_Wd1; K = 64;   N = 2048; break;
        case 5: W = Wd2; off = OFF_Wd2; K = 2048; N = 2048; break;
        default:W = Wd3; off = OFF_Wd3; K = 2048; N = 1024; break;
    }
    int k0 = blockIdx.x * 32, n0 = blockIdx.y * 32;
    if (k0 >= K || n0 >= N) return;
    __shared__ float t[32][33];
    int tx = threadIdx.x, ty = threadIdx.y;
    for (int r = ty; r < 32; r += 8)
        t[r][tx] = W[(size_t)(k0 + r) * N + n0 + tx];
    __syncthreads();
    __nv_bfloat16* Th = Wh + off;
    __nv_bfloat16* Tl = Wl + off;
    for (int r = ty; r < 32; r += 8) {
        float v = t[tx][r];
        size_t o = (size_t)(n0 + r) * K + k0 + tx;
        __nv_bfloat16 h = __float2bfloat16(v);
        Th[o] = h;
        Tl[o] = __float2bfloat16(v - __bfloat162float(h));
    }
}

// ---------------------------------------------------------------------------
// mma.sync GEMM, 4-stage pipeline, 1 sync/iter, 3-pass mma ordering.
// OUTMODE: 0 = f32 only, 1 = bf16 hi/lo pair only, 2 = both
// ---------------------------------------------------------------------------
template <int BM, int BN, int WARPS_M, int WARPS_N, int OUTMODE>
__global__ __launch_bounds__(256, 1)
void gemm_mma(const __nv_bfloat16* __restrict__ Ah, const __nv_bfloat16* __restrict__ Al,
              const __nv_bfloat16* __restrict__ Bh, const __nv_bfloat16* __restrict__ Bl,
              const float* __restrict__ bias,
              float* __restrict__ Cf,
              __nv_bfloat16* __restrict__ Ch, __nv_bfloat16* __restrict__ Cl,
              int N, int K, int act)
{
    constexpr int BK = 32;
    constexpr int STAGES = 4;
    constexpr int WM = BM / WARPS_M, WN = BN / WARPS_N;
    constexpr int MW = WM / 16, NW = WN / 8;
    constexpr int ASZ = BM * 64;   // bytes per operand per stage (32 bf16/row)
    constexpr int BSZ = BN * 64;
    constexpr int SSZ = 2 * ASZ + 2 * BSZ;

    extern __shared__ __align__(128) char sm[];
    const uint32_t sb = smem_u32(sm);
    const int tid = threadIdx.x, wid = tid >> 5, lid = tid & 31;
    const int row0 = blockIdx.y * BM, col0 = blockIdx.x * BN;
    const int KT = K / BK;

    const int wm0 = (wid % WARPS_M) * WM;
    const int wn0 = (wid / WARPS_M) * WN;
    const int mat = lid >> 3, mr = lid & 7;

    float acc[MW][NW][4];
#pragma unroll
    for (int i = 0; i < MW; i++)
#pragma unroll
        for (int j = 0; j < NW; j++)
#pragma unroll
            for (int q = 0; q < 4; q++) acc[i][j][q] = 0.0f;

    auto load_stage = [&](int kt, int s) {
        const uint32_t st = sb + s * SSZ;
        const int k0 = kt * BK;
#pragma unroll
        for (int ch = tid; ch < BM * 4; ch += 256) {
            int r = ch >> 2, c = ch & 3;
            size_t g = (size_t)(row0 + r) * K + k0 + c * 8;
            uint32_t so = st + tile_off(r, c);
            cp_async16(so, Ah + g);
            cp_async16(so + ASZ, Al + g);
        }
#pragma unroll
        for (int ch = tid; ch < BN * 4; ch += 256) {
            int r = ch >> 2, c = ch & 3;
            size_t g = (size_t)(col0 + r) * K + k0 + c * 8;
            uint32_t so = st + 2 * ASZ + tile_off(r, c);
            cp_async16(so, Bh + g);
            cp_async16(so + BSZ, Bl + g);
        }
    };

    int arow[MW], brow[NW / 2];
#pragma unroll
    for (int i = 0; i < MW; i++) arow[i] = wm0 + i * 16 + (mat & 1) * 8 + mr;
#pragma unroll
    for (int j = 0; j < NW / 2; j++) brow[j] = wn0 + j * 16 + (mat >> 1) * 8 + mr;

#pragma unroll
    for (int p = 0; p < STAGES - 1; p++) {
        if (p < KT) load_stage(p, p);
        cp_commit();
    }

    for (int kt = 0; kt < KT; kt++) {
        cp_wait<STAGES - 2>();
        __syncthreads();

        if (kt + STAGES - 1 < KT) load_stage(kt + STAGES - 1, (kt + STAGES - 1) & 3);
        cp_commit();

        const int s = kt & 3;
        const uint32_t stA  = sb + s * SSZ;
        const uint32_t stAl = stA + ASZ;
        const uint32_t stB  = stA + 2 * ASZ;
        const uint32_t stBl = stB + BSZ;

#pragma unroll
        for (int ks = 0; ks < 2; ks++) {
            uint32_t ah[MW][4], al[MW][4], bh[NW][2], bl[NW][2];
#pragma unroll
            for (int i = 0; i < MW; i++) {
                uint32_t off = tile_off(arow[i], 2 * ks + (mat >> 1));
                ldsm4(ah[i], stA + off);
                ldsm4(al[i], stAl + off);
            }
#pragma unroll
            for (int j = 0; j < NW / 2; j++) {
                uint32_t off = tile_off(brow[j], 2 * ks + (mat & 1));
                uint32_t t[4];
                ldsm4(t, stB + off);
                bh[2 * j][0] = t[0]; bh[2 * j][1] = t[1];
                bh[2 * j + 1][0] = t[2]; bh[2 * j + 1][1] = t[3];
                ldsm4(t, stBl + off);
                bl[2 * j][0] = t[0]; bl[2 * j][1] = t[1];
                bl[2 * j + 1][0] = t[2]; bl[2 * j + 1][1] = t[3];
            }
            // 3-pass ordering: per-acc order is still hh -> hl -> lh (bit-
            // identical result), but consecutive mmas hit different
            // accumulators, breaking the length-3 RAW chains.
#pragma unroll
            for (int i = 0; i < MW; i++)
#pragma unroll
                for (int j = 0; j < NW; j++)
                    mma16816(acc[i][j], ah[i], bh[j]);  // hh
#pragma unroll
            for (int i = 0; i < MW; i++)
#pragma unroll
                for (int j = 0; j < NW; j++)
                    mma16816(acc[i][j], ah[i], bl[j]);  // hl
#pragma unroll
            for (int i = 0; i < MW; i++)
#pragma unroll
                for (int j = 0; j < NW; j++)
                    mma16816(acc[i][j], al[i], bh[j]);  // lh
        }
    }

    // ---- epilogue ----
    const int lm = lid >> 2, ln2 = (lid & 3) * 2;
#pragma unroll
    for (int i = 0; i < MW; i++)
#pragma unroll
        for (int j = 0; j < NW; j++)
#pragma unroll
            for (int h = 0; h < 2; h++) {
                int gm = row0 + wm0 + i * 16 + h * 8 + lm;
                int gn = col0 + wn0 + j * 8 + ln2;
                float v0 = acc[i][j][2 * h + 0] + __ldg(bias + gn);
                float v1 = acc[i][j][2 * h + 1] + __ldg(bias + gn + 1);
                if (act == 1) { v0 = fmaxf(v0, 0.f); v1 = fmaxf(v1, 0.f); }
                else if (act == 2) {
                    v0 = 1.0f / (1.0f + expf(-v0));
                    v1 = 1.0f / (1.0f + expf(-v1));
                }
                size_t o = (size_t)gm * N + gn;
                if (OUTMODE == 0 || OUTMODE == 2)
                    *reinterpret_cast<float2*>(Cf + o) = make_float2(v0, v1);
                if (OUTMODE == 1 || OUTMODE == 2) {
                    __nv_bfloat16 h0 = __float2bfloat16(v0);
                    __nv_bfloat16 h1 = __float2bfloat16(v1);
                    __nv_bfloat16 l0 = __float2bfloat16(v0 - __bfloat162float(h0));
                    __nv_bfloat16 l1 = __float2bfloat16(v1 - __bfloat162float(h1));
                    *reinterpret_cast<__nv_bfloat162*>(Ch + o) = __halves2bfloat162(h0, h1);
                    *reinterpret_cast<__nv_bfloat162*>(Cl + o) = __halves2bfloat162(l0, l1);
                }
            }
}

// ---------------------------------------------------------------------------
// Host launch
// ---------------------------------------------------------------------------
extern "C" void kernel_launch(void* const* d_in, const int* in_sizes, int n_in,
                              void* d_out, int out_size) {
    const float* x   = (const float*)d_in[0];
    const float* We1 = (const float*)d_in[1];
    const float* be1 = (const float*)d_in[2];
    const float* We2 = (const float*)d_in[3];
    const float* be2 = (const float*)d_in[4];
    const float* We3 = (const float*)d_in[5];
    const float* be3 = (const float*)d_in[6];
    const float* Wd1 = (const float*)d_in[7];
    const float* bd1 = (const float*)d_in[8];
    const float* Wd2 = (const float*)d_in[9];
    const float* bd2 = (const float*)d_in[10];
    const float* Wd3 = (const float*)d_in[11];
    const float* bd3 = (const float*)d_in[12];

    float* out = (float*)d_out;
    float* control = out;
    float* state   = out + (size_t)BATCH * 64;

    __nv_bfloat16 *bufAh, *bufAl, *bufBh, *bufBl, *ctrlh, *ctrll, *Wh, *Wl;
    cudaGetSymbolAddress((void**)&bufAh, g_bufA_h);
    cudaGetSymbolAddress((void**)&bufAl, g_bufA_l);
    cudaGetSymbolAddress((void**)&bufBh, g_bufB_h);
    cudaGetSymbolAddress((void**)&bufBl, g_bufB_l);
    cudaGetSymbolAddress((void**)&ctrlh, g_ctrl_h);
    cudaGetSymbolAddress((void**)&ctrll, g_ctrl_l);
    cudaGetSymbolAddress((void**)&Wh, g_Wh);
    cudaGetSymbolAddress((void**)&Wl, g_Wl);

    constexpr int SMEM_BIG   = 4 * (2 * 128 * 64 + 2 * 128 * 64);  // 131072
    constexpr int SMEM_SMALL = 4 * (2 * 64 * 64 + 2 * 64 * 64);    // 65536
    cudaFuncSetAttribute((const void*)gemm_mma<128,128,4,2,0>,
                         cudaFuncAttributeMaxDynamicSharedMemorySize, SMEM_BIG);
    cudaFuncSetAttribute((const void*)gemm_mma<128,128,4,2,1>,
                         cudaFuncAttributeMaxDynamicSharedMemorySize, SMEM_BIG);
    cudaFuncSetAttribute((const void*)gemm_mma<64,64,4,2,2>,
                         cudaFuncAttributeMaxDynamicSharedMemorySize, SMEM_SMALL);

    // ---- prep: ONE launch (launch #1) ----
    prep_all<<<dim3(64, 64, 7), dim3(32, 8)>>>(
        x, bufBh, bufBl, We1, We2, We3, Wd1, Wd2, Wd3, Wh, Wl);

    // L1 (#2): x @ We1 -> relu (N=2048, K=1024)
    gemm_mma<128,128,4,2,1><<<dim3(16, 64), 256, SMEM_BIG>>>(
        bufBh, bufBl, Wh + OFF_We1, Wl + OFF_We1, be1,
        nullptr, bufAh, bufAl, 2048, 1024, 1);
    // L2 (#3): @ We2 -> relu (N=2048, K=2048)
    gemm_mma<128,128,4,2,1><<<dim3(16, 64), 256, SMEM_BIG>>>(
        bufAh, bufAl, Wh + OFF_We2, Wl + OFF_We2, be2,
        nullptr, bufBh, bufBl, 2048, 2048, 1);
    // L3 (#4): @ We3 -> sigmoid (N=64, K=2048)
    gemm_mma<64,64,4,2,2><<<dim3(1, 128), 256, SMEM_SMALL>>>(
        bufBh, bufBl, Wh + OFF_We3, Wl + OFF_We3, be3,
        control, ctrlh, ctrll, 64, 2048, 2);
    // L4 (#5): @ Wd1 -> relu (N=2048, K=64)
    gemm_mma<128,128,4,2,1><<<dim3(16, 64), 256, SMEM_BIG>>>(
        ctrlh, ctrll, Wh + OFF_Wd1, Wl + OFF_Wd1, bd1,
        nullptr, bufAh, bufAl, 2048, 64, 1);
    // L5 (#6): @ Wd2 -> relu (N=2048, K=2048)   <-- ncu -s 5 capture target
    gemm_mma<128,128,4,2,1><<<dim3(16, 64), 256, SMEM_BIG>>>(
        bufAh, bufAl, Wh + OFF_Wd2, Wl + OFF_Wd2, bd2,
        nullptr, bufBh, bufBl, 2048, 2048, 1);
    // L6 (#7): @ Wd3 -> linear f32 (N=1024, K=2048)
    gemm_mma<128,128,4,2,0><<<dim3(8, 64), 256, SMEM_BIG>>>(
        bufBh, bufBl, Wh + OFF_Wd3, Wl + OFF_Wd3, bd3,
        state, nullptr, nullptr, 1024, 2048, 0);

    (void)in_sizes; (void)n_in; (void)out_size;
}

// round 10
// speedup vs baseline: 1.2023x; 1.1082x over previous
#include <cuda_runtime.h>
#include <cuda_bf16.h>
#include <cstdint>
#include <math.h>

// ============================================================================
// AutoEncoder via mma.sync (HMMA), bf16 hi/lo split (3 products).
// R7: 3-stage ring (98KB smem) + __launch_bounds__(256,2) -> 2 CTAs/SM,
//     16 warps/SM for latency hiding. Numerics identical to R6.
// ============================================================================

#define BATCH 8192

__device__ __forceinline__ uint32_t smem_u32(const void* p) {
    uint32_t a;
    asm("{ .reg .u64 t; cvta.to.shared.u64 t, %1; cvt.u32.u64 %0, t; }"
        : "=r"(a) : "l"(p));
    return a;
}
__device__ __forceinline__ void cp_async16(uint32_t dst, const void* src) {
    asm volatile("cp.async.cg.shared.global [%0], [%1], 16;" :: "r"(dst), "l"(src));
}
__device__ __forceinline__ void cp_commit() {
    asm volatile("cp.async.commit_group;" ::: "memory");
}
template <int N> __device__ __forceinline__ void cp_wait() {
    asm volatile("cp.async.wait_group %0;" :: "n"(N) : "memory");
}
__device__ __forceinline__ void ldsm4(uint32_t* r, uint32_t a) {
    asm volatile("ldmatrix.sync.aligned.m8n8.x4.shared.b16 {%0,%1,%2,%3}, [%4];"
                 : "=r"(r[0]), "=r"(r[1]), "=r"(r[2]), "=r"(r[3]) : "r"(a));
}
__device__ __forceinline__ void mma16816(float* d, const uint32_t* a, const uint32_t* b) {
    asm volatile("mma.sync.aligned.m16n8k16.row.col.f32.bf16.bf16.f32 "
                 "{%0,%1,%2,%3}, {%4,%5,%6,%7}, {%8,%9}, {%0,%1,%2,%3};"
                 : "+f"(d[0]), "+f"(d[1]), "+f"(d[2]), "+f"(d[3])
                 : "r"(a[0]), "r"(a[1]), "r"(a[2]), "r"(a[3]),
                   "r"(b[0]), "r"(b[1]));
}
// 64B logical rows packed pairwise into 128B atoms + SW128 XOR swizzle.
__device__ __forceinline__ uint32_t tile_off(int r, int c) {
    uint32_t o = ((uint32_t)(r >> 1) << 7) + ((uint32_t)(r & 1) << 6) +
                 ((uint32_t)c << 4);
    return o ^ ((o >> 3) & 0x70);
}

// ---------------------------------------------------------------------------
// Device global scratch
// ---------------------------------------------------------------------------
__device__ __align__(16) __nv_bfloat16 g_bufA_h[(size_t)BATCH * 2048];
__device__ __align__(16) __nv_bfloat16 g_bufA_l[(size_t)BATCH * 2048];
__device__ __align__(16) __nv_bfloat16 g_bufB_h[(size_t)BATCH * 2048];
__device__ __align__(16) __nv_bfloat16 g_bufB_l[(size_t)BATCH * 2048];
__device__ __align__(16) __nv_bfloat16 g_ctrl_h[(size_t)BATCH * 64];
__device__ __align__(16) __nv_bfloat16 g_ctrl_l[(size_t)BATCH * 64];

#define OFF_We1 0u
#define OFF_We2 (OFF_We1 + 2048u*1024u)
#define OFF_We3 (OFF_We2 + 2048u*2048u)
#define OFF_Wd1 (OFF_We3 + 64u*2048u)
#define OFF_Wd2 (OFF_Wd1 + 2048u*64u)
#define OFF_Wd3 (OFF_Wd2 + 2048u*2048u)
#define W_TOTAL (OFF_Wd3 + 1024u*2048u)
__device__ __align__(16) __nv_bfloat16 g_Wh[W_TOTAL];
__device__ __align__(16) __nv_bfloat16 g_Wl[W_TOTAL];

// ---------------------------------------------------------------------------
// Fused prep: ONE launch. z=0: split x; z=1..6: transpose+split weights.
// ---------------------------------------------------------------------------
__global__ void prep_all(const float* __restrict__ x,
                         __nv_bfloat16* __restrict__ xh, __nv_bfloat16* __restrict__ xl,
                         const float* We1, const float* We2, const float* We3,
                         const float* Wd1, const float* Wd2, const float* Wd3,
                         __nv_bfloat16* __restrict__ Wh, __nv_bfloat16* __restrict__ Wl)
{
    const int z = blockIdx.z;
    if (z == 0) {
        int tid = threadIdx.y * 32 + threadIdx.x;
        int bid = blockIdx.y * 64 + blockIdx.x;
        int base = (bid * 256 + tid) * 2;
#pragma unroll
        for (int u = 0; u < 2; u++) {
            int i = base + u;
            float4 v = reinterpret_cast<const float4*>(x)[i];
            __nv_bfloat16 h0 = __float2bfloat16(v.x), h1 = __float2bfloat16(v.y);
            __nv_bfloat16 h2 = __float2bfloat16(v.z), h3 = __float2bfloat16(v.w);
            __nv_bfloat16 l0 = __float2bfloat16(v.x - __bfloat162float(h0));
            __nv_bfloat16 l1 = __float2bfloat16(v.y - __bfloat162float(h1));
            __nv_bfloat16 l2 = __float2bfloat16(v.z - __bfloat162float(h2));
            __nv_bfloat16 l3 = __float2bfloat16(v.w - __bfloat162float(h3));
            reinterpret_cast<__nv_bfloat162*>(xh)[i * 2 + 0] = __halves2bfloat162(h0, h1);
            reinterpret_cast<__nv_bfloat162*>(xh)[i * 2 + 1] = __halves2bfloat162(h2, h3);
            reinterpret_cast<__nv_bfloat162*>(xl)[i * 2 + 0] = __halves2bfloat162(l0, l1);
            reinterpret_cast<__nv_bfloat162*>(xl)[i * 2 + 1] = __halves2bfloat162(l2, l3);
        }
        return;
    }
    const float* W; uint32_t off; int K, N;
    switch (z) {
        case 1: W = We1; off = OFF_We1; K = 1024; N = 2048; break;
        case 2: W = We2; off = OFF_We2; K = 2048; N = 2048; break;
        case 3: W = We3; off = OFF_We3; K = 2048; N = 64;   break;
        case 4: W = Wd1; off = OFF_Wd1; K = 64;   N = 2048; break;
        case 5: W = Wd2; off = OFF_Wd2; K = 2048; N = 2048; break;
        default:W = Wd3; off = OFF_Wd3; K = 2048; N = 1024; break;
    }
    int k0 = blockIdx.x * 32, n0 = blockIdx.y * 32;
    if (k0 >= K || n0 >= N) return;
    __shared__ float t[32][33];
    int tx = threadIdx.x, ty = threadIdx.y;
    for (int r = ty; r < 32; r += 8)
        t[r][tx] = W[(size_t)(k0 + r) * N + n0 + tx];
    __syncthreads();
    __nv_bfloat16* Th = Wh + off;
    __nv_bfloat16* Tl = Wl + off;
    for (int r = ty; r < 32; r += 8) {
        float v = t[tx][r];
        size_t o = (size_t)(n0 + r) * K + k0 + tx;
        __nv_bfloat16 h = __float2bfloat16(v);
        Th[o] = h;
        Tl[o] = __float2bfloat16(v - __bfloat162float(h));
    }
}

// ---------------------------------------------------------------------------
// mma.sync GEMM, 3-stage pipeline, 1 sync/iter, 3-pass mma ordering,
// 2 CTAs/SM. OUTMODE: 0 = f32 only, 1 = bf16 hi/lo pair only, 2 = both
// ---------------------------------------------------------------------------
template <int BM, int BN, int WARPS_M, int WARPS_N, int STAGES, int MINB, int OUTMODE>
__global__ __launch_bounds__(WARPS_M * WARPS_N * 32, MINB)
void gemm_mma(const __nv_bfloat16* __restrict__ Ah, const __nv_bfloat16* __restrict__ Al,
              const __nv_bfloat16* __restrict__ Bh, const __nv_bfloat16* __restrict__ Bl,
              const float* __restrict__ bias,
              float* __restrict__ Cf,
              __nv_bfloat16* __restrict__ Ch, __nv_bfloat16* __restrict__ Cl,
              int N, int K, int act)
{
    constexpr int THREADS = WARPS_M * WARPS_N * 32;
    constexpr int BK = 32;
    constexpr int WM = BM / WARPS_M, WN = BN / WARPS_N;
    constexpr int MW = WM / 16, NW = WN / 8;
    constexpr int ASZ = BM * 64;   // bytes per operand per stage (32 bf16/row)
    constexpr int BSZ = BN * 64;
    constexpr int SSZ = 2 * ASZ + 2 * BSZ;

    extern __shared__ __align__(128) char sm[];
    const uint32_t sb = smem_u32(sm);
    const int tid = threadIdx.x, wid = tid >> 5, lid = tid & 31;
    const int row0 = blockIdx.y * BM, col0 = blockIdx.x * BN;
    const int KT = K / BK;

    const int wm0 = (wid % WARPS_M) * WM;
    const int wn0 = (wid / WARPS_M) * WN;
    const int mat = lid >> 3, mr = lid & 7;

    float acc[MW][NW][4];
#pragma unroll
    for (int i = 0; i < MW; i++)
#pragma unroll
        for (int j = 0; j < NW; j++)
#pragma unroll
            for (int q = 0; q < 4; q++) acc[i][j][q] = 0.0f;

    auto load_stage = [&](int kt, int s) {
        const uint32_t st = sb + s * SSZ;
        const int k0 = kt * BK;
#pragma unroll
        for (int ch = tid; ch < BM * 4; ch += THREADS) {
            int r = ch >> 2, c = ch & 3;
            size_t g = (size_t)(row0 + r) * K + k0 + c * 8;
            uint32_t so = st + tile_off(r, c);
            cp_async16(so, Ah + g);
            cp_async16(so + ASZ, Al + g);
        }
#pragma unroll
        for (int ch = tid; ch < BN * 4; ch += THREADS) {
            int r = ch >> 2, c = ch & 3;
            size_t g = (size_t)(col0 + r) * K + k0 + c * 8;
            uint32_t so = st + 2 * ASZ + tile_off(r, c);
            cp_async16(so, Bh + g);
            cp_async16(so + BSZ, Bl + g);
        }
    };

    int arow[MW], brow[NW / 2];
#pragma unroll
    for (int i = 0; i < MW; i++) arow[i] = wm0 + i * 16 + (mat & 1) * 8 + mr;
#pragma unroll
    for (int j = 0; j < NW / 2; j++) brow[j] = wn0 + j * 16 + (mat >> 1) * 8 + mr;

#pragma unroll
    for (int p = 0; p < STAGES - 1; p++) {
        if (p < KT) load_stage(p, p);
        cp_commit();
    }

    for (int kt = 0; kt < KT; kt++) {
        cp_wait<STAGES - 2>();
        __syncthreads();

        if (kt + STAGES - 1 < KT) load_stage(kt + STAGES - 1, (kt + STAGES - 1) % STAGES);
        cp_commit();

        const int s = kt % STAGES;
        const uint32_t stA  = sb + s * SSZ;
        const uint32_t stAl = stA + ASZ;
        const uint32_t stB  = stA + 2 * ASZ;
        const uint32_t stBl = stB + BSZ;

#pragma unroll
        for (int ks = 0; ks < 2; ks++) {
            uint32_t ah[MW][4], al[MW][4], bh[NW][2], bl[NW][2];
#pragma unroll
            for (int i = 0; i < MW; i++) {
                uint32_t off = tile_off(arow[i], 2 * ks + (mat >> 1));
                ldsm4(ah[i], stA + off);
                ldsm4(al[i], stAl + off);
            }
#pragma unroll
            for (int j = 0; j < NW / 2; j++) {
                uint32_t off = tile_off(brow[j], 2 * ks + (mat & 1));
                uint32_t t[4];
                ldsm4(t, stB + off);
                bh[2 * j][0] = t[0]; bh[2 * j][1] = t[1];
                bh[2 * j + 1][0] = t[2]; bh[2 * j + 1][1] = t[3];
                ldsm4(t, stBl + off);
                bl[2 * j][0] = t[0]; bl[2 * j][1] = t[1];
                bl[2 * j + 1][0] = t[2]; bl[2 * j + 1][1] = t[3];
            }
            // per-acc order hh -> hl -> lh (bit-identical), chains broken
#pragma unroll
            for (int i = 0; i < MW; i++)
#pragma unroll
                for (int j = 0; j < NW; j++)
                    mma16816(acc[i][j], ah[i], bh[j]);  // hh
#pragma unroll
            for (int i = 0; i < MW; i++)
#pragma unroll
                for (int j = 0; j < NW; j++)
                    mma16816(acc[i][j], ah[i], bl[j]);  // hl
#pragma unroll
            for (int i = 0; i < MW; i++)
#pragma unroll
                for (int j = 0; j < NW; j++)
                    mma16816(acc[i][j], al[i], bh[j]);  // lh
        }
    }

    // ---- epilogue ----
    const int lm = lid >> 2, ln2 = (lid & 3) * 2;
#pragma unroll
    for (int i = 0; i < MW; i++)
#pragma unroll
        for (int j = 0; j < NW; j++)
#pragma unroll
            for (int h = 0; h < 2; h++) {
                int gm = row0 + wm0 + i * 16 + h * 8 + lm;
                int gn = col0 + wn0 + j * 8 + ln2;
                float v0 = acc[i][j][2 * h + 0] + __ldg(bias + gn);
                float v1 = acc[i][j][2 * h + 1] + __ldg(bias + gn + 1);
                if (act == 1) { v0 = fmaxf(v0, 0.f); v1 = fmaxf(v1, 0.f); }
                else if (act == 2) {
                    v0 = 1.0f / (1.0f + expf(-v0));
                    v1 = 1.0f / (1.0f + expf(-v1));
                }
                size_t o = (size_t)gm * N + gn;
                if (OUTMODE == 0 || OUTMODE == 2)
                    *reinterpret_cast<float2*>(Cf + o) = make_float2(v0, v1);
                if (OUTMODE == 1 || OUTMODE == 2) {
                    __nv_bfloat16 h0 = __float2bfloat16(v0);
                    __nv_bfloat16 h1 = __float2bfloat16(v1);
                    __nv_bfloat16 l0 = __float2bfloat16(v0 - __bfloat162float(h0));
                    __nv_bfloat16 l1 = __float2bfloat16(v1 - __bfloat162float(h1));
                    *reinterpret_cast<__nv_bfloat162*>(Ch + o) = __halves2bfloat162(h0, h1);
                    *reinterpret_cast<__nv_bfloat162*>(Cl + o) = __halves2bfloat162(l0, l1);
                }
            }
}

// ---------------------------------------------------------------------------
// Host launch
// ---------------------------------------------------------------------------
extern "C" void kernel_launch(void* const* d_in, const int* in_sizes, int n_in,
                              void* d_out, int out_size) {
    const float* x   = (const float*)d_in[0];
    const float* We1 = (const float*)d_in[1];
    const float* be1 = (const float*)d_in[2];
    const float* We2 = (const float*)d_in[3];
    const float* be2 = (const float*)d_in[4];
    const float* We3 = (const float*)d_in[5];
    const float* be3 = (const float*)d_in[6];
    const float* Wd1 = (const float*)d_in[7];
    const float* bd1 = (const float*)d_in[8];
    const float* Wd2 = (const float*)d_in[9];
    const float* bd2 = (const float*)d_in[10];
    const float* Wd3 = (const float*)d_in[11];
    const float* bd3 = (const float*)d_in[12];

    float* out = (float*)d_out;
    float* control = out;
    float* state   = out + (size_t)BATCH * 64;

    __nv_bfloat16 *bufAh, *bufAl, *bufBh, *bufBl, *ctrlh, *ctrll, *Wh, *Wl;
    cudaGetSymbolAddress((void**)&bufAh, g_bufA_h);
    cudaGetSymbolAddress((void**)&bufAl, g_bufA_l);
    cudaGetSymbolAddress((void**)&bufBh, g_bufB_h);
    cudaGetSymbolAddress((void**)&bufBl, g_bufB_l);
    cudaGetSymbolAddress((void**)&ctrlh, g_ctrl_h);
    cudaGetSymbolAddress((void**)&ctrll, g_ctrl_l);
    cudaGetSymbolAddress((void**)&Wh, g_Wh);
    cudaGetSymbolAddress((void**)&Wl, g_Wl);

    // big: 3 stages x (16KB A-pair + 16KB B-pair) = 98304 B -> 2 CTAs/SM
    constexpr int SMEM_BIG   = 3 * (2 * 128 * 64 + 2 * 128 * 64);  // 98304
    constexpr int SMEM_SMALL = 4 * (2 * 64 * 64 + 2 * 64 * 64);    // 65536
    cudaFuncSetAttribute((const void*)gemm_mma<128,128,4,2,3,2,0>,
                         cudaFuncAttributeMaxDynamicSharedMemorySize, SMEM_BIG);
    cudaFuncSetAttribute((const void*)gemm_mma<128,128,4,2,3,2,1>,
                         cudaFuncAttributeMaxDynamicSharedMemorySize, SMEM_BIG);
    cudaFuncSetAttribute((const void*)gemm_mma<64,64,4,2,4,1,2>,
                         cudaFuncAttributeMaxDynamicSharedMemorySize, SMEM_SMALL);

    // ---- prep: ONE launch (#1) ----
    prep_all<<<dim3(64, 64, 7), dim3(32, 8)>>>(
        x, bufBh, bufBl, We1, We2, We3, Wd1, Wd2, Wd3, Wh, Wl);

    // L1 (#2): x @ We1 -> relu (N=2048, K=1024)
    gemm_mma<128,128,4,2,3,2,1><<<dim3(16, 64), 256, SMEM_BIG>>>(
        bufBh, bufBl, Wh + OFF_We1, Wl + OFF_We1, be1,
        nullptr, bufAh, bufAl, 2048, 1024, 1);
    // L2 (#3): @ We2 -> relu (N=2048, K=2048)
    gemm_mma<128,128,4,2,3,2,1><<<dim3(16, 64), 256, SMEM_BIG>>>(
        bufAh, bufAl, Wh + OFF_We2, Wl + OFF_We2, be2,
        nullptr, bufBh, bufBl, 2048, 2048, 1);
    // L3 (#4): @ We3 -> sigmoid (N=64, K=2048)
    gemm_mma<64,64,4,2,4,1,2><<<dim3(1, 128), 256, SMEM_SMALL>>>(
        bufBh, bufBl, Wh + OFF_We3, Wl + OFF_We3, be3,
        control, ctrlh, ctrll, 64, 2048, 2);
    // L4 (#5): @ Wd1 -> relu (N=2048, K=64)
    gemm_mma<128,128,4,2,3,2,1><<<dim3(16, 64), 256, SMEM_BIG>>>(
        ctrlh, ctrll, Wh + OFF_Wd1, Wl + OFF_Wd1, bd1,
        nullptr, bufAh, bufAl, 2048, 64, 1);
    // L5 (#6): @ Wd2 -> relu (N=2048, K=2048)   <-- ncu capture target
    gemm_mma<128,128,4,2,3,2,1><<<dim3(16, 64), 256, SMEM_BIG>>>(
        bufAh, bufAl, Wh + OFF_Wd2, Wl + OFF_Wd2, bd2,
        nullptr, bufBh, bufBl, 2048, 2048, 1);
    // L6 (#7): @ Wd3 -> linear f32 (N=1024, K=2048)
    gemm_mma<128,128,4,2,3,2,0><<<dim3(8, 64), 256, SMEM_BIG>>>(
        bufBh, bufBl, Wh + OFF_Wd3, Wl + OFF_Wd3, bd3,
        state, nullptr, nullptr, 1024, 2048, 0);

    (void)in_sizes; (void)n_in; (void)out_size;
}

// round 12
// speedup vs baseline: 1.7709x; 1.4729x over previous
#include <cuda_runtime.h>
#include <cuda_fp16.h>
#include <cstdint>
#include <math.h>

// ============================================================================
// AutoEncoder via mma.sync (HMMA fp16), activation hi/lo split (2 products).
//   D = (ah + al) @ W_fp16 ; weights rounded to fp16 (err ~2^-13),
//   activations split exactly (err ~2^-22). 2 MMAs per tile instead of 3.
// R10: work reduction from R7's bf16 3-term scheme.
// ============================================================================

#define BATCH 8192

__device__ __forceinline__ uint32_t smem_u32(const void* p) {
    uint32_t a;
    asm("{ .reg .u64 t; cvta.to.shared.u64 t, %1; cvt.u32.u64 %0, t; }"
        : "=r"(a) : "l"(p));
    return a;
}
__device__ __forceinline__ void cp_async16(uint32_t dst, const void* src) {
    asm volatile("cp.async.cg.shared.global [%0], [%1], 16;" :: "r"(dst), "l"(src));
}
__device__ __forceinline__ void cp_commit() {
    asm volatile("cp.async.commit_group;" ::: "memory");
}
template <int N> __device__ __forceinline__ void cp_wait() {
    asm volatile("cp.async.wait_group %0;" :: "n"(N) : "memory");
}
__device__ __forceinline__ void ldsm4(uint32_t* r, uint32_t a) {
    asm volatile("ldmatrix.sync.aligned.m8n8.x4.shared.b16 {%0,%1,%2,%3}, [%4];"
                 : "=r"(r[0]), "=r"(r[1]), "=r"(r[2]), "=r"(r[3]) : "r"(a));
}
__device__ __forceinline__ void mma16816(float* d, const uint32_t* a, const uint32_t* b) {
    asm volatile("mma.sync.aligned.m16n8k16.row.col.f32.f16.f16.f32 "
                 "{%0,%1,%2,%3}, {%4,%5,%6,%7}, {%8,%9}, {%0,%1,%2,%3};"
                 : "+f"(d[0]), "+f"(d[1]), "+f"(d[2]), "+f"(d[3])
                 : "r"(a[0]), "r"(a[1]), "r"(a[2]), "r"(a[3]),
                   "r"(b[0]), "r"(b[1]));
}
// 64B logical rows packed pairwise into 128B atoms + SW128 XOR swizzle.
__device__ __forceinline__ uint32_t tile_off(int r, int c) {
    uint32_t o = ((uint32_t)(r >> 1) << 7) + ((uint32_t)(r & 1) << 6) +
                 ((uint32_t)c << 4);
    return o ^ ((o >> 3) & 0x70);
}

// ---------------------------------------------------------------------------
// Device global scratch
// ---------------------------------------------------------------------------
__device__ __align__(16) __half g_bufA_h[(size_t)BATCH * 2048];
__device__ __align__(16) __half g_bufA_l[(size_t)BATCH * 2048];
__device__ __align__(16) __half g_bufB_h[(size_t)BATCH * 2048];
__device__ __align__(16) __half g_bufB_l[(size_t)BATCH * 2048];
__device__ __align__(16) __half g_ctrl_h[(size_t)BATCH * 64];
__device__ __align__(16) __half g_ctrl_l[(size_t)BATCH * 64];

#define OFF_We1 0u
#define OFF_We2 (OFF_We1 + 2048u*1024u)
#define OFF_We3 (OFF_We2 + 2048u*2048u)
#define OFF_Wd1 (OFF_We3 + 64u*2048u)
#define OFF_Wd2 (OFF_Wd1 + 2048u*64u)
#define OFF_Wd3 (OFF_Wd2 + 2048u*2048u)
#define W_TOTAL (OFF_Wd3 + 1024u*2048u)
__device__ __align__(16) __half g_W[W_TOTAL];

// ---------------------------------------------------------------------------
// Fused prep: ONE launch. z=0: split x into fp16 hi/lo; z=1..6: transpose
// weights to fp16 (single precision-rounded copy).
// ---------------------------------------------------------------------------
__global__ void prep_all(const float* __restrict__ x,
                         __half* __restrict__ xh, __half* __restrict__ xl,
                         const float* We1, const float* We2, const float* We3,
                         const float* Wd1, const float* Wd2, const float* Wd3,
                         __half* __restrict__ W)
{
    const int z = blockIdx.z;
    if (z == 0) {
        int tid = threadIdx.y * 32 + threadIdx.x;
        int bid = blockIdx.y * 64 + blockIdx.x;
        int base = (bid * 256 + tid) * 2;
#pragma unroll
        for (int u = 0; u < 2; u++) {
            int i = base + u;
            float4 v = reinterpret_cast<const float4*>(x)[i];
            __half h0 = __float2half_rn(v.x), h1 = __float2half_rn(v.y);
            __half h2 = __float2half_rn(v.z), h3 = __float2half_rn(v.w);
            __half l0 = __float2half_rn(v.x - __half2float(h0));
            __half l1 = __float2half_rn(v.y - __half2float(h1));
            __half l2 = __float2half_rn(v.z - __half2float(h2));
            __half l3 = __float2half_rn(v.w - __half2float(h3));
            reinterpret_cast<__half2*>(xh)[i * 2 + 0] = __halves2half2(h0, h1);
            reinterpret_cast<__half2*>(xh)[i * 2 + 1] = __halves2half2(h2, h3);
            reinterpret_cast<__half2*>(xl)[i * 2 + 0] = __halves2half2(l0, l1);
            reinterpret_cast<__half2*>(xl)[i * 2 + 1] = __halves2half2(l2, l3);
        }
        return;
    }
    const float* Wi; uint32_t off; int K, N;
    switch (z) {
        case 1: Wi = We1; off = OFF_We1; K = 1024; N = 2048; break;
        case 2: Wi = We2; off = OFF_We2; K = 2048; N = 2048; break;
        case 3: Wi = We3; off = OFF_We3; K = 2048; N = 64;   break;
        case 4: Wi = Wd1; off = OFF_Wd1; K = 64;   N = 2048; break;
        case 5: Wi = Wd2; off = OFF_Wd2; K = 2048; N = 2048; break;
        default:Wi = Wd3; off = OFF_Wd3; K = 2048; N = 1024; break;
    }
    int k0 = blockIdx.x * 32, n0 = blockIdx.y * 32;
    if (k0 >= K || n0 >= N) return;
    __shared__ float t[32][33];
    int tx = threadIdx.x, ty = threadIdx.y;
    for (int r = ty; r < 32; r += 8)
        t[r][tx] = Wi[(size_t)(k0 + r) * N + n0 + tx];
    __syncthreads();
    __half* T = W + off;
    for (int r = ty; r < 32; r += 8) {
        size_t o = (size_t)(n0 + r) * K + k0 + tx;
        T[o] = __float2half_rn(t[tx][r]);
    }
}

// ---------------------------------------------------------------------------
// mma.sync fp16 GEMM: C = act((Ah+Al) @ W^T + bias), 2 MMA products.
// 3-stage ring, 1 sync/iter, 2 CTAs/SM for big tiles.
// OUTMODE: 0 = f32 only, 1 = fp16 hi/lo pair only, 2 = both
// ---------------------------------------------------------------------------
template <int BM, int BN, int WARPS_M, int WARPS_N, int STAGES, int MINB, int OUTMODE>
__global__ __launch_bounds__(WARPS_M * WARPS_N * 32, MINB)
void gemm_mma(const __half* __restrict__ Ah, const __half* __restrict__ Al,
              const __half* __restrict__ B,
              const float* __restrict__ bias,
              float* __restrict__ Cf,
              __half* __restrict__ Ch, __half* __restrict__ Cl,
              int N, int K, int act)
{
    constexpr int THREADS = WARPS_M * WARPS_N * 32;
    constexpr int BK = 32;
    constexpr int WM = BM / WARPS_M, WN = BN / WARPS_N;
    constexpr int MW = WM / 16, NW = WN / 8;
    constexpr int ASZ = BM * 64;           // bytes per A operand per stage
    constexpr int BSZ = BN * 64;           // B single operand
    constexpr int SSZ = 2 * ASZ + BSZ;

    extern __shared__ __align__(128) char sm[];
    const uint32_t sb = smem_u32(sm);
    const int tid = threadIdx.x, wid = tid >> 5, lid = tid & 31;
    const int row0 = blockIdx.y * BM, col0 = blockIdx.x * BN;
    const int KT = K / BK;

    const int wm0 = (wid % WARPS_M) * WM;
    const int wn0 = (wid / WARPS_M) * WN;
    const int mat = lid >> 3, mr = lid & 7;

    float acc[MW][NW][4];
#pragma unroll
    for (int i = 0; i < MW; i++)
#pragma unroll
        for (int j = 0; j < NW; j++)
#pragma unroll
            for (int q = 0; q < 4; q++) acc[i][j][q] = 0.0f;

    auto load_stage = [&](int kt, int s) {
        const uint32_t st = sb + s * SSZ;
        const int k0 = kt * BK;
#pragma unroll
        for (int ch = tid; ch < BM * 4; ch += THREADS) {
            int r = ch >> 2, c = ch & 3;
            size_t g = (size_t)(row0 + r) * K + k0 + c * 8;
            uint32_t so = st + tile_off(r, c);
            cp_async16(so, Ah + g);
            cp_async16(so + ASZ, Al + g);
        }
#pragma unroll
        for (int ch = tid; ch < BN * 4; ch += THREADS) {
            int r = ch >> 2, c = ch & 3;
            size_t g = (size_t)(col0 + r) * K + k0 + c * 8;
            cp_async16(st + 2 * ASZ + tile_off(r, c), B + g);
        }
    };

    int arow[MW], brow[NW / 2];
#pragma unroll
    for (int i = 0; i < MW; i++) arow[i] = wm0 + i * 16 + (mat & 1) * 8 + mr;
#pragma unroll
    for (int j = 0; j < NW / 2; j++) brow[j] = wn0 + j * 16 + (mat >> 1) * 8 + mr;

#pragma unroll
    for (int p = 0; p < STAGES - 1; p++) {
        if (p < KT) load_stage(p, p);
        cp_commit();
    }

    for (int kt = 0; kt < KT; kt++) {
        cp_wait<STAGES - 2>();
        __syncthreads();

        if (kt + STAGES - 1 < KT) load_stage(kt + STAGES - 1, (kt + STAGES - 1) % STAGES);
        cp_commit();

        const int s = kt % STAGES;
        const uint32_t stA  = sb + s * SSZ;
        const uint32_t stAl = stA + ASZ;
        const uint32_t stB  = stA + 2 * ASZ;

#pragma unroll
        for (int ks = 0; ks < 2; ks++) {
            uint32_t ah[MW][4], al[MW][4], bh[NW][2];
#pragma unroll
            for (int i = 0; i < MW; i++) {
                uint32_t off = tile_off(arow[i], 2 * ks + (mat >> 1));
                ldsm4(ah[i], stA + off);
                ldsm4(al[i], stAl + off);
            }
#pragma unroll
            for (int j = 0; j < NW / 2; j++) {
                uint32_t off = tile_off(brow[j], 2 * ks + (mat & 1));
                uint32_t t[4];
                ldsm4(t, stB + off);
                bh[2 * j][0] = t[0]; bh[2 * j][1] = t[1];
                bh[2 * j + 1][0] = t[2]; bh[2 * j + 1][1] = t[3];
            }
            // 2 passes: hi*B then lo*B (per-acc order fixed; chains broken)
#pragma unroll
            for (int i = 0; i < MW; i++)
#pragma unroll
                for (int j = 0; j < NW; j++)
                    mma16816(acc[i][j], ah[i], bh[j]);
#pragma unroll
            for (int i = 0; i < MW; i++)
#pragma unroll
                for (int j = 0; j < NW; j++)
                    mma16816(acc[i][j], al[i], bh[j]);
        }
    }

    // ---- epilogue ----
    const int lm = lid >> 2, ln2 = (lid & 3) * 2;
#pragma unroll
    for (int i = 0; i < MW; i++)
#pragma unroll
        for (int j = 0; j < NW; j++)
#pragma unroll
            for (int h = 0; h < 2; h++) {
                int gm = row0 + wm0 + i * 16 + h * 8 + lm;
                int gn = col0 + wn0 + j * 8 + ln2;
                float v0 = acc[i][j][2 * h + 0] + __ldg(bias + gn);
                float v1 = acc[i][j][2 * h + 1] + __ldg(bias + gn + 1);
                if (act == 1) { v0 = fmaxf(v0, 0.f); v1 = fmaxf(v1, 0.f); }
                else if (act == 2) {
                    v0 = 1.0f / (1.0f + expf(-v0));
                    v1 = 1.0f / (1.0f + expf(-v1));
                }
                size_t o = (size_t)gm * N + gn;
                if (OUTMODE == 0 || OUTMODE == 2)
                    *reinterpret_cast<float2*>(Cf + o) = make_float2(v0, v1);
                if (OUTMODE == 1 || OUTMODE == 2) {
                    __half h0 = __float2half_rn(v0);
                    __half h1 = __float2half_rn(v1);
                    __half l0 = __float2half_rn(v0 - __half2float(h0));
                    __half l1 = __float2half_rn(v1 - __half2float(h1));
                    *reinterpret_cast<__half2*>(Ch + o) = __halves2half2(h0, h1);
                    *reinterpret_cast<__half2*>(Cl + o) = __halves2half2(l0, l1);
                }
            }
}

// ---------------------------------------------------------------------------
// Host launch
// ---------------------------------------------------------------------------
extern "C" void kernel_launch(void* const* d_in, const int* in_sizes, int n_in,
                              void* d_out, int out_size) {
    const float* x   = (const float*)d_in[0];
    const float* We1 = (const float*)d_in[1];
    const float* be1 = (const float*)d_in[2];
    const float* We2 = (const float*)d_in[3];
    const float* be2 = (const float*)d_in[4];
    const float* We3 = (const float*)d_in[5];
    const float* be3 = (const float*)d_in[6];
    const float* Wd1 = (const float*)d_in[7];
    const float* bd1 = (const float*)d_in[8];
    const float* Wd2 = (const float*)d_in[9];
    const float* bd2 = (const float*)d_in[10];
    const float* Wd3 = (const float*)d_in[11];
    const float* bd3 = (const float*)d_in[12];

    float* out = (float*)d_out;
    float* control = out;
    float* state   = out + (size_t)BATCH * 64;

    __half *bufAh, *bufAl, *bufBh, *bufBl, *ctrlh, *ctrll, *W;
    cudaGetSymbolAddress((void**)&bufAh, g_bufA_h);
    cudaGetSymbolAddress((void**)&bufAl, g_bufA_l);
    cudaGetSymbolAddress((void**)&bufBh, g_bufB_h);
    cudaGetSymbolAddress((void**)&bufBl, g_bufB_l);
    cudaGetSymbolAddress((void**)&ctrlh, g_ctrl_h);
    cudaGetSymbolAddress((void**)&ctrll, g_ctrl_l);
    cudaGetSymbolAddress((void**)&W, g_W);

    // big: 3 stages x (16KB A-pair + 8KB B) = 73728 B -> 2 CTAs/SM
    constexpr int SMEM_BIG   = 3 * (2 * 128 * 64 + 128 * 64);  // 73728
    constexpr int SMEM_SMALL = 4 * (2 * 64 * 64 + 64 * 64);    // 49152
    cudaFuncSetAttribute((const void*)gemm_mma<128,128,4,2,3,2,0>,
                         cudaFuncAttributeMaxDynamicSharedMemorySize, SMEM_BIG);
    cudaFuncSetAttribute((const void*)gemm_mma<128,128,4,2,3,2,1>,
                         cudaFuncAttributeMaxDynamicSharedMemorySize, SMEM_BIG);
    cudaFuncSetAttribute((const void*)gemm_mma<64,64,4,2,4,1,2>,
                         cudaFuncAttributeMaxDynamicSharedMemorySize, SMEM_SMALL);

    // ---- prep: ONE launch (#1) ----
    prep_all<<<dim3(64, 64, 7), dim3(32, 8)>>>(
        x, bufBh, bufBl, We1, We2, We3, Wd1, Wd2, Wd3, W);

    // L1 (#2): x @ We1 -> relu (N=2048, K=1024)
    gemm_mma<128,128,4,2,3,2,1><<<dim3(16, 64), 256, SMEM_BIG>>>(
        bufBh, bufBl, W + OFF_We1, be1,
        nullptr, bufAh, bufAl, 2048, 1024, 1);
    // L2 (#3): @ We2 -> relu (N=2048, K=2048)
    gemm_mma<128,128,4,2,3,2,1><<<dim3(16, 64), 256, SMEM_BIG>>>(
        bufAh, bufAl, W + OFF_We2, be2,
        nullptr, bufBh, bufBl, 2048, 2048, 1);
    // L3 (#4): @ We3 -> sigmoid (N=64, K=2048)
    gemm_mma<64,64,4,2,4,1,2><<<dim3(1, 128), 256, SMEM_SMALL>>>(
        bufBh, bufBl, W + OFF_We3, be3,
        control, ctrlh, ctrll, 64, 2048, 2);
    // L4 (#5): @ Wd1 -> relu (N=2048, K=64)
    gemm_mma<128,128,4,2,3,2,1><<<dim3(16, 64), 256, SMEM_BIG>>>(
        ctrlh, ctrll, W + OFF_Wd1, bd1,
        nullptr, bufAh, bufAl, 2048, 64, 1);
    // L5 (#6): @ Wd2 -> relu (N=2048, K=2048)   <-- ncu capture target
    gemm_mma<128,128,4,2,3,2,1><<<dim3(16, 64), 256, SMEM_BIG>>>(
        bufAh, bufAl, W + OFF_Wd2, bd2,
        nullptr, bufBh, bufBl, 2048, 2048, 1);
    // L6 (#7): @ Wd3 -> linear f32 (N=1024, K=2048)
    gemm_mma<128,128,4,2,3,2,0><<<dim3(8, 64), 256, SMEM_BIG>>>(
        bufBh, bufBl, W + OFF_Wd3, bd3,
        state, nullptr, nullptr, 1024, 2048, 0);

    (void)in_sizes; (void)n_in; (void)out_size;
}